// round 1
// baseline (speedup 1.0000x reference)
#include <cuda_runtime.h>
#include <cstdint>

#define NTOK 32768
#define DIM  1024
#define HID  512
#define NEXP 8
#define TILE_T 32
#define MAXTILES 1040   // NTOK/32 + NEXP, rounded up

// ---------------- scratch (device globals; no allocations allowed) ----------
__device__ int   g_sel[NTOK];
__device__ int   g_blockHist[128][8];
__device__ int   g_blockOff[128][8];
__device__ int   g_count[8];
__device__ int   g_padBase[8];
__device__ int   g_numTiles;
__device__ int   g_tileExpert[MAXTILES];
__device__ int   g_tileBase[MAXTILES];
__device__ int   g_tileValid[MAXTILES];
__device__ int   g_tileRange[9];
__device__ int   g_perm[NTOK + 8 * TILE_T];
__device__ float g_scores[NTOK + 8 * TILE_T];
__device__ float g_max[8];
__device__ float g_sum[8];
__device__ float g_partial[(size_t)MAXTILES * DIM];

// ---------------- K1: gate logits + argmax + per-block histogram ------------
__global__ void k_gate(const float* __restrict__ x, const float* __restrict__ gw) {
    __shared__ float sG[NEXP * DIM];   // 32 KB
    __shared__ int sHist[8];
    int tid = threadIdx.x;
    if (tid < 8) sHist[tid] = 0;
    float4* sG4 = (float4*)sG;
    const float4* g4 = (const float4*)gw;
#pragma unroll
    for (int i = 0; i < 8; i++) sG4[tid + i * 256] = g4[tid + i * 256];
    __syncthreads();

    int warp = tid >> 5, lane = tid & 31;
    int base = blockIdx.x * 256 + warp * 32;
    for (int it = 0; it < 32; it++) {
        int n = base + it;
        const float* xr = x + (size_t)n * DIM;
        float acc[8];
#pragma unroll
        for (int e = 0; e < 8; e++) acc[e] = 0.f;
        for (int k = 0; k < 32; k++) {
            int dd = lane + k * 32;
            float xv = xr[dd];
#pragma unroll
            for (int e = 0; e < 8; e++) acc[e] = fmaf(xv, sG[e * DIM + dd], acc[e]);
        }
#pragma unroll
        for (int e = 0; e < 8; e++)
#pragma unroll
            for (int o = 16; o; o >>= 1) acc[e] += __shfl_xor_sync(~0u, acc[e], o);
        if (lane == 0) {
            int best = 0; float bv = acc[0];
#pragma unroll
            for (int e = 1; e < 8; e++) if (acc[e] > bv) { bv = acc[e]; best = e; }
            g_sel[n] = best;
            atomicAdd(&sHist[best], 1);
        }
    }
    __syncthreads();
    if (tid < 8) g_blockHist[blockIdx.x][tid] = sHist[tid];
}

// ---------------- K2: scan histograms, build tile descriptors ---------------
__global__ void k_scan() {
    __shared__ int sH[128 * 8];
    __shared__ int sOff[128 * 8];
    __shared__ int sCount[8], sPad[8];
    int tid = threadIdx.x;  // 256
    for (int i = tid; i < 1024; i += 256) sH[i] = ((int*)g_blockHist)[i];
    __syncthreads();
    if (tid < 8) {
        int off = 0;
        for (int b = 0; b < 128; b++) { sOff[b * 8 + tid] = off; off += sH[b * 8 + tid]; }
        sCount[tid] = off;
        g_count[tid] = off;
    }
    __syncthreads();
    if (tid == 0) {
        int pb = 0;
        for (int e = 0; e < 8; e++) {
            sPad[e] = pb; g_padBase[e] = pb;
            pb += ((sCount[e] + TILE_T - 1) / TILE_T) * TILE_T;
        }
        int idx = 0;
        for (int e = 0; e < 8; e++) {
            g_tileRange[e] = idx;
            int c = sCount[e];
            for (int i = 0; i * TILE_T < c; i++) {
                g_tileExpert[idx] = e;
                g_tileBase[idx]   = sPad[e] + i * TILE_T;
                g_tileValid[idx]  = min(TILE_T, c - i * TILE_T);
                idx++;
            }
        }
        g_tileRange[8] = idx;
        g_numTiles = idx;
    }
    __syncthreads();
    for (int i = tid; i < 1024; i += 256) {
        int e = i & 7;
        ((int*)g_blockOff)[i] = sPad[e] + sOff[i];
    }
}

// ---------------- K3: stable scatter (deterministic counting sort) ----------
__global__ void k_scatter() {
    __shared__ int sSel[256];
    int tid = threadIdx.x;
    int n = blockIdx.x * 256 + tid;
    int e = g_sel[n];
    sSel[tid] = e;
    __syncthreads();
    int rank = 0;
    for (int i = 0; i < tid; i++) rank += (sSel[i] == e);
    g_perm[g_blockOff[blockIdx.x][e] + rank] = n;
}

// ---------------- K4: main score GEMM (packed f32x2 FMA) --------------------
__global__ void __launch_bounds__(256, 2)
k_score(const float* __restrict__ x, const float* __restrict__ W1,
        const float* __restrict__ b1, const float* __restrict__ w2,
        const float* __restrict__ b2) {
    int tile = blockIdx.x;
    if (tile >= g_numTiles) return;
    int e = g_tileExpert[tile], tbase = g_tileBase[tile], tvalid = g_tileValid[tile];

    __shared__ float  sW[16 * HID];      // 32 KB W1 chunk [16 d][512 h]
    __shared__ float2 sX[TILE_T * 16];   // x duplicated into both lanes
    __shared__ int    sTok[TILE_T];
    __shared__ float  sRed[8][8];

    int tid = threadIdx.x;
    if (tid < TILE_T) {
        int t = tid;
        sTok[t] = g_perm[tbase + min(t, tvalid - 1)];
    }
    __syncthreads();

    int ht = tid & 63;   // 64 groups of 8 h
    int tt = tid >> 6;   // 4 groups of 8 tokens
    const float* W1e = W1 + (size_t)e * (DIM * HID);

    unsigned long long acc[32];
#pragma unroll
    for (int i = 0; i < 32; i++) acc[i] = 0ULL;

    for (int d0 = 0; d0 < DIM; d0 += 16) {
        __syncthreads();
        {   // stage W1 chunk: 16 rows * 512 floats contiguous = 2048 float4
            const float4* g4 = (const float4*)(W1e + (size_t)d0 * HID);
            float4* s4 = (float4*)sW;
#pragma unroll
            for (int i = 0; i < 8; i++) s4[tid + i * 256] = g4[tid + i * 256];
        }
        {   // stage x chunk: 32 tokens * 16 floats, duplicated
            int t = tid >> 3, j = tid & 7;
            const float2 xv = *(const float2*)(x + (size_t)sTok[t] * DIM + d0 + j * 2);
            sX[t * 16 + j * 2]     = make_float2(xv.x, xv.x);
            sX[t * 16 + j * 2 + 1] = make_float2(xv.y, xv.y);
        }
        __syncthreads();
#pragma unroll
        for (int dt = 0; dt < 16; dt++) {
            const ulonglong2* wr = (const ulonglong2*)(sW + dt * HID + ht * 8);
            ulonglong2 w01 = wr[0];
            ulonglong2 w23 = wr[1];
            const unsigned long long* xp =
                (const unsigned long long*)(sX + (tt * 8) * 16 + dt);
#pragma unroll
            for (int t = 0; t < 8; t++) {
                unsigned long long xv = xp[(size_t)t * 16];
                asm("fma.rn.f32x2 %0, %1, %2, %0;" : "+l"(acc[t * 4 + 0]) : "l"(xv), "l"(w01.x));
                asm("fma.rn.f32x2 %0, %1, %2, %0;" : "+l"(acc[t * 4 + 1]) : "l"(xv), "l"(w01.y));
                asm("fma.rn.f32x2 %0, %1, %2, %0;" : "+l"(acc[t * 4 + 2]) : "l"(xv), "l"(w23.x));
                asm("fma.rn.f32x2 %0, %1, %2, %0;" : "+l"(acc[t * 4 + 3]) : "l"(xv), "l"(w23.y));
            }
        }
    }

    // epilogue: +b1, tanh, dot w2 -> per-thread partial over its 8 h
    int h0 = ht * 8;
    const float* b1e = b1 + e * HID;
    const float* w2e = w2 + e * HID;
    float p[8];
#pragma unroll
    for (int t = 0; t < 8; t++) {
        float s = 0.f;
#pragma unroll
        for (int hp = 0; hp < 4; hp++) {
            float2 v = *(float2*)&acc[t * 4 + hp];
            int h = h0 + hp * 2;
            float hv0 = tanhf(v.x + b1e[h]);
            float hv1 = tanhf(v.y + b1e[h + 1]);
            s = fmaf(hv0, w2e[h], s);
            s = fmaf(hv1, w2e[h + 1], s);
        }
        p[t] = s;
    }
#pragma unroll
    for (int t = 0; t < 8; t++)
#pragma unroll
        for (int o = 16; o; o >>= 1) p[t] += __shfl_xor_sync(~0u, p[t], o);

    int warp = tid >> 5, lane = tid & 31;
    __syncthreads();
    if (lane == 0) {
#pragma unroll
        for (int t = 0; t < 8; t++) sRed[warp][t] = p[t];
    }
    __syncthreads();
    if (tid < TILE_T) {
        int t = tid;
        int w0 = (t >> 3) * 2;
        float sc = sRed[w0][t & 7] + sRed[w0 + 1][t & 7] + b2[e];
        g_scores[tbase + t] = sc;   // padded slots written but never read
    }
}

// ---------------- K5: per-expert softmax stats -------------------------------
__global__ void k_softmax() {
    int e = blockIdx.x;
    int cnt = g_count[e], base = g_padBase[e];
    __shared__ float sred[256];
    int tid = threadIdx.x;
    float m = -3.0e38f;
    for (int i = tid; i < cnt; i += 256) m = fmaxf(m, g_scores[base + i]);
    sred[tid] = m; __syncthreads();
    for (int s = 128; s; s >>= 1) {
        if (tid < s) sred[tid] = fmaxf(sred[tid], sred[tid + s]);
        __syncthreads();
    }
    float mx = sred[0]; __syncthreads();
    float sum = 0.f;
    for (int i = tid; i < cnt; i += 256) sum += expf(g_scores[base + i] - mx);
    sred[tid] = sum; __syncthreads();
    for (int s = 128; s; s >>= 1) {
        if (tid < s) sred[tid] += sred[tid + s];
        __syncthreads();
    }
    if (tid == 0) { g_max[e] = mx; g_sum[e] = (cnt > 0) ? sred[0] : 1.f; }
}

// ---------------- K6: pooled partials (per-tile, per-128-d slice) ------------
__global__ void k_poolA(const float* __restrict__ x) {
    int tile = blockIdx.x;
    if (tile >= g_numTiles) return;
    int e = g_tileExpert[tile], tbase = g_tileBase[tile], tvalid = g_tileValid[tile];
    __shared__ float sWt[TILE_T];
    __shared__ int   sN[TILE_T];
    int tid = threadIdx.x;  // 128
    if (tid < TILE_T) {
        if (tid < tvalid) {
            sWt[tid] = expf(g_scores[tbase + tid] - g_max[e]) / g_sum[e];
            sN[tid]  = g_perm[tbase + tid];
        } else { sWt[tid] = 0.f; sN[tid] = 0; }
    }
    __syncthreads();
    int d = blockIdx.y * 128 + tid;
    float acc = 0.f;
    for (int t = 0; t < tvalid; t++)
        acc = fmaf(sWt[t], x[(size_t)sN[t] * DIM + d], acc);
    g_partial[(size_t)tile * DIM + d] = acc;
}

// ---------------- K7: fixed-order reduction over tiles -> output -------------
__global__ void k_poolB(float* __restrict__ out) {
    int e = blockIdx.x;
    int d = threadIdx.x;  // 1024
    float acc = 0.f;
    int t0 = g_tileRange[e], t1 = g_tileRange[e + 1];
    for (int t = t0; t < t1; t++)
        acc += g_partial[(size_t)t * DIM + d];
    out[e * DIM + d] = acc;
}

// ---------------- entry ------------------------------------------------------
extern "C" void kernel_launch(void* const* d_in, const int* in_sizes, int n_in,
                              void* d_out, int out_size) {
    const float* x   = (const float*)d_in[0];
    const float* gw  = (const float*)d_in[1];
    const float* W1  = (const float*)d_in[2];
    const float* b1  = (const float*)d_in[3];
    const float* w2  = (const float*)d_in[4];
    const float* b2  = (const float*)d_in[5];
    float* out = (float*)d_out;

    k_gate<<<128, 256>>>(x, gw);
    k_scan<<<1, 256>>>();
    k_scatter<<<128, 256>>>();
    k_score<<<MAXTILES, 256>>>(x, W1, b1, w2, b2);
    k_softmax<<<8, 256>>>();
    dim3 gA(MAXTILES, 8);
    k_poolA<<<gA, 128>>>(x);
    k_poolB<<<8, 1024>>>(out);
}

// round 3
// speedup vs baseline: 2.1759x; 2.1759x over previous
#include <cuda_runtime.h>
#include <cuda_bf16.h>
#include <cstdint>

#define NTOK 32768
#define DIM  1024
#define HID  512
#define NEXP 8
#define TILE_T 128
#define MAXTILES 264   // 32768/128 + 8

// ---------------- scratch (device globals; no allocations allowed) ----------
__device__ int   g_sel[NTOK];
__device__ int   g_blockHist[128][8];
__device__ int   g_blockOff[128][8];
__device__ int   g_count[8];
__device__ int   g_padBase[8];
__device__ int   g_numTiles;
__device__ int   g_tileExpert[MAXTILES];
__device__ int   g_tileBase[MAXTILES];
__device__ int   g_tileValid[MAXTILES];
__device__ int   g_tileRange[9];
__device__ int   g_perm[NTOK + NEXP * TILE_T];
__device__ float g_scores[NTOK + NEXP * TILE_T];
__device__ float g_scorePart[(size_t)MAXTILES * 4 * 128];
__device__ float g_max[8];
__device__ float g_sum[8];
__device__ float g_partial[(size_t)MAXTILES * DIM];
// inputs converted to bf16 hi/lo
__device__ __nv_bfloat16 g_xhi[(size_t)NTOK * DIM];
__device__ __nv_bfloat16 g_xlo[(size_t)NTOK * DIM];
// W1 converted to bf16 hi/lo, TRANSPOSED to [E][H][D]
__device__ __nv_bfloat16 g_w1hi[(size_t)NEXP * HID * DIM];
__device__ __nv_bfloat16 g_w1lo[(size_t)NEXP * HID * DIM];

// ---------------- PTX helpers (all sm_80-era; no 'a' features) --------------
__device__ __forceinline__ uint32_t smem_u32(const void* p) {
    uint32_t a;
    asm("{ .reg .u64 t; cvta.to.shared.u64 t, %1; cvt.u32.u64 %0, t; }" : "=r"(a) : "l"(p));
    return a;
}
#define SW128(o) (((uint32_t)(o)) ^ ((((uint32_t)(o)) >> 3) & 0x70))

#define CPA16(dst, src) \
    asm volatile("cp.async.cg.shared.global [%0], [%1], 16;" :: "r"(dst), "l"(src))

#define LDSM4(r, addr) \
    asm volatile("ldmatrix.sync.aligned.m8n8.x4.shared.b16 {%0,%1,%2,%3}, [%4];" \
        : "=r"((r)[0]), "=r"((r)[1]), "=r"((r)[2]), "=r"((r)[3]) : "r"(addr))
#define LDSM2(r, addr) \
    asm volatile("ldmatrix.sync.aligned.m8n8.x2.shared.b16 {%0,%1}, [%2];" \
        : "=r"((r)[0]), "=r"((r)[1]) : "r"(addr))

#define MMA_BF16(d, a, b) \
    asm volatile("mma.sync.aligned.m16n8k16.row.col.f32.bf16.bf16.f32 " \
        "{%0,%1,%2,%3}, {%4,%5,%6,%7}, {%8,%9}, {%0,%1,%2,%3};" \
        : "+f"((d)[0]), "+f"((d)[1]), "+f"((d)[2]), "+f"((d)[3]) \
        : "r"((a)[0]), "r"((a)[1]), "r"((a)[2]), "r"((a)[3]), \
          "r"((b)[0]), "r"((b)[1]))

// ---------------- K0a: convert + transpose W1 --------------------------------
__global__ void k_cvtW(const float* __restrict__ W1) {
    __shared__ float t[32][33];
    int e = blockIdx.z, db = blockIdx.x, hb = blockIdx.y;
    int tx = threadIdx.x, ty = threadIdx.y;  // 32 x 8
    const float* src = W1 + ((size_t)e * DIM + db * 32) * HID + hb * 32;
#pragma unroll
    for (int j = 0; j < 4; j++)
        t[ty + j * 8][tx] = src[(size_t)(ty + j * 8) * HID + tx];
    __syncthreads();
#pragma unroll
    for (int j = 0; j < 4; j++) {
        float v = t[tx][ty + j * 8];
        __nv_bfloat16 hi = __float2bfloat16_rn(v);
        __nv_bfloat16 lo = __float2bfloat16_rn(v - __bfloat162float(hi));
        size_t o = ((size_t)e * HID + hb * 32 + ty + j * 8) * DIM + db * 32 + tx;
        g_w1hi[o] = hi;
        g_w1lo[o] = lo;
    }
}

// ---------------- K0b: convert X to bf16 hi/lo --------------------------------
__global__ void k_cvtX(const float* __restrict__ x) {
    size_t i = (size_t)blockIdx.x * 256 + threadIdx.x;
    const float4* x4 = (const float4*)x;
    uint2* hi = (uint2*)g_xhi;
    uint2* lo = (uint2*)g_xlo;
    const size_t total = (size_t)NTOK * DIM / 4;
    for (; i < total; i += (size_t)gridDim.x * 256) {
        float4 v = x4[i];
        __nv_bfloat162 h01 = __float22bfloat162_rn(make_float2(v.x, v.y));
        __nv_bfloat162 h23 = __float22bfloat162_rn(make_float2(v.z, v.w));
        float2 f01 = __bfloat1622float2(h01);
        float2 f23 = __bfloat1622float2(h23);
        __nv_bfloat162 l01 = __float22bfloat162_rn(make_float2(v.x - f01.x, v.y - f01.y));
        __nv_bfloat162 l23 = __float22bfloat162_rn(make_float2(v.z - f23.x, v.w - f23.y));
        hi[i] = make_uint2(*(uint32_t*)&h01, *(uint32_t*)&h23);
        lo[i] = make_uint2(*(uint32_t*)&l01, *(uint32_t*)&l23);
    }
}

// ---------------- K1: gate logits + argmax + per-block histogram ------------
__global__ void k_gate(const float* __restrict__ x, const float* __restrict__ gw) {
    __shared__ float sG[NEXP * DIM];
    __shared__ int sHist[8];
    int tid = threadIdx.x;
    if (tid < 8) sHist[tid] = 0;
    float4* sG4 = (float4*)sG;
    const float4* g4 = (const float4*)gw;
#pragma unroll
    for (int i = 0; i < 8; i++) sG4[tid + i * 256] = g4[tid + i * 256];
    __syncthreads();

    int warp = tid >> 5, lane = tid & 31;
    int base = blockIdx.x * 256 + warp * 32;
    for (int it = 0; it < 32; it++) {
        int n = base + it;
        const float* xr = x + (size_t)n * DIM;
        float acc[8];
#pragma unroll
        for (int e = 0; e < 8; e++) acc[e] = 0.f;
        for (int k = 0; k < 32; k++) {
            int dd = lane + k * 32;
            float xv = xr[dd];
#pragma unroll
            for (int e = 0; e < 8; e++) acc[e] = fmaf(xv, sG[e * DIM + dd], acc[e]);
        }
#pragma unroll
        for (int e = 0; e < 8; e++)
#pragma unroll
            for (int o = 16; o; o >>= 1) acc[e] += __shfl_xor_sync(~0u, acc[e], o);
        if (lane == 0) {
            int best = 0; float bv = acc[0];
#pragma unroll
            for (int e = 1; e < 8; e++) if (acc[e] > bv) { bv = acc[e]; best = e; }
            g_sel[n] = best;
            atomicAdd(&sHist[best], 1);
        }
    }
    __syncthreads();
    if (tid < 8) g_blockHist[blockIdx.x][tid] = sHist[tid];
}

// ---------------- K2: scan histograms, build tile descriptors ---------------
__global__ void k_scan() {
    __shared__ int sH[128 * 8];
    __shared__ int sOff[128 * 8];
    __shared__ int sCount[8], sPad[8];
    int tid = threadIdx.x;  // 256
    for (int i = tid; i < 1024; i += 256) sH[i] = ((int*)g_blockHist)[i];
    __syncthreads();
    if (tid < 8) {
        int off = 0;
        for (int b = 0; b < 128; b++) { sOff[b * 8 + tid] = off; off += sH[b * 8 + tid]; }
        sCount[tid] = off;
        g_count[tid] = off;
    }
    __syncthreads();
    if (tid == 0) {
        int pb = 0;
        for (int e = 0; e < 8; e++) {
            sPad[e] = pb; g_padBase[e] = pb;
            pb += ((sCount[e] + TILE_T - 1) / TILE_T) * TILE_T;
        }
        int idx = 0;
        for (int e = 0; e < 8; e++) {
            g_tileRange[e] = idx;
            int c = sCount[e];
            for (int i = 0; i * TILE_T < c; i++) {
                g_tileExpert[idx] = e;
                g_tileBase[idx]   = sPad[e] + i * TILE_T;
                g_tileValid[idx]  = min(TILE_T, c - i * TILE_T);
                idx++;
            }
        }
        g_tileRange[8] = idx;
        g_numTiles = idx;
    }
    __syncthreads();
    for (int i = tid; i < 1024; i += 256) {
        int e = i & 7;
        ((int*)g_blockOff)[i] = sPad[e] + sOff[i];
    }
}

// ---------------- K3: stable scatter (deterministic counting sort) ----------
__global__ void k_scatter() {
    __shared__ int sSel[256];
    int tid = threadIdx.x;
    int n = blockIdx.x * 256 + tid;
    int e = g_sel[n];
    sSel[tid] = e;
    __syncthreads();
    int rank = 0;
    for (int i = 0; i < tid; i++) rank += (sSel[i] == e);
    g_perm[g_blockOff[blockIdx.x][e] + rank] = n;
}

// ---------------- K4: score GEMM on HMMA (3-term split-bf16) -----------------
// CTA: 128 tokens x 128 hidden, K=1024 in 16 chunks of 64, double-buffered.
#define KC 64
#define SMX 0        // [stage][hi/lo] 16KB each -> 64KB
#define SMW 65536    // [stage][hi/lo] 16KB each -> 64KB
#define SMB1 131072
#define SMW2 131584
#define SMRED 132096
#define SMTOK 133120
#define SMTOT 133632

__device__ __forceinline__ void load_chunk(uint32_t smb, const int* sTok,
                                           const char* xhiB, const char* xloB,
                                           const char* whiB, const char* wloB,
                                           int d0, int stage, int tid) {
#pragma unroll
    for (int it = 0; it < 4; it++) {
        int seg = it * 256 + tid;           // 0..1023
        int row = seg >> 3, c16 = seg & 7;  // 16B column block
        uint32_t doff = SW128((uint32_t)(row * 128 + c16 * 16));
        size_t xsrc = (size_t)sTok[row] * (DIM * 2) + d0 * 2 + c16 * 16;
        CPA16(smb + SMX + stage * 32768 + doff,         xhiB + xsrc);
        CPA16(smb + SMX + stage * 32768 + 16384 + doff, xloB + xsrc);
        size_t wsrc = (size_t)row * (DIM * 2) + d0 * 2 + c16 * 16;
        CPA16(smb + SMW + stage * 32768 + doff,         whiB + wsrc);
        CPA16(smb + SMW + stage * 32768 + 16384 + doff, wloB + wsrc);
    }
    asm volatile("cp.async.commit_group;" ::: "memory");
}

__global__ void __launch_bounds__(256, 1)
k_score(const float* __restrict__ b1, const float* __restrict__ w2) {
    int tile = blockIdx.x;
    if (tile >= g_numTiles) return;
    int nc = blockIdx.y;
    int e = g_tileExpert[tile], tbase = g_tileBase[tile], tvalid = g_tileValid[tile];

    extern __shared__ char sm[];
    uint32_t smb = smem_u32(sm);
    int tid = threadIdx.x, wid = tid >> 5, lane = tid & 31;

    int*   sTok = (int*)(sm + SMTOK);
    float* b1s  = (float*)(sm + SMB1);
    float* w2s  = (float*)(sm + SMW2);
    float* sRed = (float*)(sm + SMRED);

    if (tid < 128) {
        sTok[tid] = g_perm[tbase + min(tid, tvalid - 1)];
        int h = nc * 128 + tid;
        b1s[tid] = b1[e * HID + h];
        w2s[tid] = w2[e * HID + h];
    }
    __syncthreads();

    const char* xhiB = (const char*)g_xhi;
    const char* xloB = (const char*)g_xlo;
    const char* whiB = (const char*)(g_w1hi + ((size_t)e * HID + (size_t)nc * 128) * DIM);
    const char* wloB = (const char*)(g_w1lo + ((size_t)e * HID + (size_t)nc * 128) * DIM);

    int wm = wid >> 1, wn = wid & 1;
    int m0 = wm * 32, n0 = wn * 64;

    // per-lane ldmatrix byte offsets (pre-swizzle)
    uint32_t aBase = (uint32_t)((m0 + (lane & 15)) * 128 + (lane >> 4) * 16);
    uint32_t bBase = (uint32_t)((n0 + (lane & 7)) * 128 + ((lane >> 3) & 1) * 16);

    float acc[2][8][4];
#pragma unroll
    for (int mt = 0; mt < 2; mt++)
#pragma unroll
        for (int nt = 0; nt < 8; nt++)
#pragma unroll
            for (int j = 0; j < 4; j++) acc[mt][nt][j] = 0.f;

    load_chunk(smb, sTok, xhiB, xloB, whiB, wloB, 0, 0, tid);

    for (int i = 0; i < 16; i++) {
        int s = i & 1;
        if (i + 1 < 16) {
            load_chunk(smb, sTok, xhiB, xloB, whiB, wloB, (i + 1) * KC, 1 - s, tid);
            asm volatile("cp.async.wait_group 1;" ::: "memory");
        } else {
            asm volatile("cp.async.wait_group 0;" ::: "memory");
        }
        __syncthreads();

        uint32_t xh = smb + SMX + s * 32768;
        uint32_t xl = xh + 16384;
        uint32_t wh = smb + SMW + s * 32768;
        uint32_t wl = wh + 16384;
#pragma unroll
        for (int kk = 0; kk < 4; kk++) {
            uint32_t ah[2][4], al[2][4];
#pragma unroll
            for (int mt = 0; mt < 2; mt++) {
                uint32_t off = SW128(aBase + mt * 2048 + kk * 32);
                LDSM4(ah[mt], xh + off);
                LDSM4(al[mt], xl + off);
            }
#pragma unroll
            for (int nt = 0; nt < 8; nt++) {
                uint32_t off = SW128(bBase + nt * 1024 + kk * 32);
                uint32_t bh[2], bl[2];
                LDSM2(bh, wh + off);
                LDSM2(bl, wl + off);
#pragma unroll
                for (int mt = 0; mt < 2; mt++) {
                    MMA_BF16(acc[mt][nt], ah[mt], bh);
                    MMA_BF16(acc[mt][nt], al[mt], bh);
                    MMA_BF16(acc[mt][nt], ah[mt], bl);
                }
            }
        }
        __syncthreads();
    }

    // epilogue: +b1, tanh, dot w2 over this CTA's 128 h-cols
    int g = lane >> 2, qc = lane & 3;
    float rs[4] = {0.f, 0.f, 0.f, 0.f};
#pragma unroll
    for (int mt = 0; mt < 2; mt++)
#pragma unroll
        for (int nt = 0; nt < 8; nt++) {
            int hl = wn * 64 + nt * 8 + qc * 2;
            float w20 = w2s[hl], w21 = w2s[hl + 1];
            float bb0 = b1s[hl], bb1 = b1s[hl + 1];
            rs[mt * 2 + 0] += tanhf(acc[mt][nt][0] + bb0) * w20
                            + tanhf(acc[mt][nt][1] + bb1) * w21;
            rs[mt * 2 + 1] += tanhf(acc[mt][nt][2] + bb0) * w20
                            + tanhf(acc[mt][nt][3] + bb1) * w21;
        }
#pragma unroll
    for (int j = 0; j < 4; j++) {
        rs[j] += __shfl_xor_sync(~0u, rs[j], 1);
        rs[j] += __shfl_xor_sync(~0u, rs[j], 2);
    }
    if (qc == 0) {
        sRed[wn * 128 + m0 + g]      = rs[0];
        sRed[wn * 128 + m0 + g + 8]  = rs[1];
        sRed[wn * 128 + m0 + g + 16] = rs[2];
        sRed[wn * 128 + m0 + g + 24] = rs[3];
    }
    __syncthreads();
    if (tid < 128)
        g_scorePart[((size_t)tile * 4 + nc) * 128 + tid] = sRed[tid] + sRed[128 + tid];
}

// ---------------- K4b: fixed-order reduce of score partials ------------------
__global__ void k_scoreRed(const float* __restrict__ b2) {
    int tile = blockIdx.x;
    if (tile >= g_numTiles) return;
    int t = threadIdx.x;
    float s = b2[g_tileExpert[tile]];
#pragma unroll
    for (int ncc = 0; ncc < 4; ncc++)
        s += g_scorePart[((size_t)tile * 4 + ncc) * 128 + t];
    g_scores[g_tileBase[tile] + t] = s;
}

// ---------------- K5: per-expert softmax stats -------------------------------
__global__ void k_softmax() {
    int e = blockIdx.x;
    int cnt = g_count[e], base = g_padBase[e];
    __shared__ float sred[256];
    int tid = threadIdx.x;
    float m = -3.0e38f;
    for (int i = tid; i < cnt; i += 256) m = fmaxf(m, g_scores[base + i]);
    sred[tid] = m; __syncthreads();
    for (int s = 128; s; s >>= 1) {
        if (tid < s) sred[tid] = fmaxf(sred[tid], sred[tid + s]);
        __syncthreads();
    }
    float mx = sred[0]; __syncthreads();
    float sum = 0.f;
    for (int i = tid; i < cnt; i += 256) sum += expf(g_scores[base + i] - mx);
    sred[tid] = sum; __syncthreads();
    for (int s = 128; s; s >>= 1) {
        if (tid < s) sred[tid] += sred[tid + s];
        __syncthreads();
    }
    if (tid == 0) { g_max[e] = mx; g_sum[e] = (cnt > 0) ? sred[0] : 1.f; }
}

// ---------------- K6: pooled partials ----------------------------------------
__global__ void k_poolA(const float* __restrict__ x) {
    int tile = blockIdx.x;
    if (tile >= g_numTiles) return;
    int e = g_tileExpert[tile], tbase = g_tileBase[tile], tvalid = g_tileValid[tile];
    __shared__ float sWt[TILE_T];
    __shared__ int   sN[TILE_T];
    int tid = threadIdx.x;  // 128
    if (tid < TILE_T) {
        if (tid < tvalid) {
            sWt[tid] = expf(g_scores[tbase + tid] - g_max[e]) / g_sum[e];
            sN[tid]  = g_perm[tbase + tid];
        } else { sWt[tid] = 0.f; sN[tid] = 0; }
    }
    __syncthreads();
    int d = blockIdx.y * 128 + tid;
    float acc = 0.f;
#pragma unroll 4
    for (int t = 0; t < tvalid; t++)
        acc = fmaf(sWt[t], x[(size_t)sN[t] * DIM + d], acc);
    g_partial[(size_t)tile * DIM + d] = acc;
}

// ---------------- K7: fixed-order reduction over tiles -> output -------------
__global__ void k_poolB(float* __restrict__ out) {
    int e = blockIdx.x;
    int d = threadIdx.x;  // 1024
    float acc = 0.f;
    int t0 = g_tileRange[e], t1 = g_tileRange[e + 1];
    for (int t = t0; t < t1; t++)
        acc += g_partial[(size_t)t * DIM + d];
    out[e * DIM + d] = acc;
}

// ---------------- entry ------------------------------------------------------
extern "C" void kernel_launch(void* const* d_in, const int* in_sizes, int n_in,
                              void* d_out, int out_size) {
    const float* x   = (const float*)d_in[0];
    const float* gw  = (const float*)d_in[1];
    const float* W1  = (const float*)d_in[2];
    const float* b1  = (const float*)d_in[3];
    const float* w2  = (const float*)d_in[4];
    const float* b2  = (const float*)d_in[5];
    float* out = (float*)d_out;

    cudaFuncSetAttribute(k_score, cudaFuncAttributeMaxDynamicSharedMemorySize, SMTOT);

    k_cvtW<<<dim3(32, 16, 8), dim3(32, 8)>>>(W1);
    k_cvtX<<<8192, 256>>>(x);
    k_gate<<<128, 256>>>(x, gw);
    k_scan<<<1, 256>>>();
    k_scatter<<<128, 256>>>();
    k_score<<<dim3(MAXTILES, 4), 256, SMTOT>>>(b1, w2);
    k_scoreRed<<<MAXTILES, 128>>>(b2);
    k_softmax<<<8, 256>>>();
    k_poolA<<<dim3(MAXTILES, 8), 128>>>(x);
    k_poolB<<<8, 1024>>>(out);
}